// round 16
// baseline (speedup 1.0000x reference)
#include <cuda_runtime.h>
#include <cuda_fp16.h>
#include <math.h>
#include <stdint.h>

#define BATCH 16384

// Scratch arenas (__device__ globals). Activations are single fp16 planes.
__device__ float g_bufA[(size_t)BATCH * 2048];
__device__ float g_bufB[(size_t)BATCH * 2048];
__device__ float g_bufC[(size_t)BATCH * 2048];
__device__ float g_x51[(size_t)BATCH * 20];
__device__ float g_x52[(size_t)BATCH * 11];
__device__ __half g_wh[20971520];   // fp16 W2|W31|W32|W41|W42

// ---------------- helpers ----------------
__device__ __forceinline__ uint32_t smem_u32(const void* p) {
    uint32_t a;
    asm("{ .reg .u64 t; cvta.to.shared.u64 t, %1; cvt.u32.u64 %0, t; }" : "=r"(a) : "l"(p));
    return a;
}

#define CP_ASYNC16(smem_addr, gptr) \
    asm volatile("cp.async.cg.shared.global [%0], [%1], 16;" :: "r"(smem_addr), "l"(gptr))
#define CP_COMMIT()  asm volatile("cp.async.commit_group;" ::: "memory")
#define CP_WAIT2()   asm volatile("cp.async.wait_group 2;" ::: "memory")

#define LDSM4(r, a) \
    asm volatile("ldmatrix.sync.aligned.m8n8.x4.shared.b16 {%0,%1,%2,%3}, [%4];" \
        : "=r"((r)[0]), "=r"((r)[1]), "=r"((r)[2]), "=r"((r)[3]) : "r"(a))

#define MMA16816(d, a, b0, b1) \
    asm volatile("mma.sync.aligned.m16n8k16.row.col.f32.f16.f16.f32 " \
        "{%0,%1,%2,%3}, {%4,%5,%6,%7}, {%8,%9}, {%0,%1,%2,%3};" \
        : "+f"((d)[0]), "+f"((d)[1]), "+f"((d)[2]), "+f"((d)[3]) \
        : "r"((a)[0]), "r"((a)[1]), "r"((a)[2]), "r"((a)[3]), \
          "r"(b0), "r"(b1))

// ---------------- weight convert: 5 weights fp32 -> fp16, one launch ----
__global__ void wconvert_kernel(const float* __restrict__ W2,
                                const float* __restrict__ W31,
                                const float* __restrict__ W32,
                                const float* __restrict__ W41,
                                const float* __restrict__ W42,
                                __half* __restrict__ dst)
{
    int i = blockIdx.x * blockDim.x + threadIdx.x;   // float4 index
    const float* src; size_t si, dbase;
    if      (i < 1048576) { src = W2;  si = i;           dbase = 0; }
    else if (i < 1572864) { src = W31; si = i - 1048576; dbase = 4194304; }
    else if (i < 2097152) { src = W32; si = i - 1572864; dbase = 6291456; }
    else if (i < 2359296) { src = W41; si = i - 2097152; dbase = 8388608; }
    else if (i < 2621440) { src = W42; si = i - 2359296; dbase = 9437184; }
    else return;
    float4 w = reinterpret_cast<const float4*>(src)[si];
    __half2 a = __floats2half2_rn(w.x, w.y);
    __half2 b = __floats2half2_rn(w.z, w.w);
    uint2 v;
    v.x = *reinterpret_cast<uint32_t*>(&a);
    v.y = *reinterpret_cast<uint32_t*>(&b);
    *reinterpret_cast<uint2*>(dst + dbase + si * 4) = v;
}

// ---------------- layer 1 (K=4) -> fp16 plane; 8 outputs/thread ----------
__global__ void layer1_kernel(const float* __restrict__ x,
                              const float* __restrict__ W1,
                              const float* __restrict__ b1,
                              __half* __restrict__ h1)
{
    int m = blockIdx.x;
    int n0 = threadIdx.x * 8;
    float4 xv = reinterpret_cast<const float4*>(x)[m];
    __half2 o[4];
#pragma unroll
    for (int p = 0; p < 4; ++p) {
        float s[2];
#pragma unroll
        for (int q = 0; q < 2; ++q) {
            int n = n0 + p * 2 + q;
            float4 wv = reinterpret_cast<const float4*>(W1)[n];
            float v = fmaf(xv.x, wv.x, fmaf(xv.y, wv.y, fmaf(xv.z, wv.z, xv.w * wv.w))) + b1[n];
            s[q] = fmaxf(v, 0.f);
        }
        o[p] = __floats2half2_rn(s[0], s[1]);
    }
    *reinterpret_cast<uint4*>(h1 + (size_t)m * 2048 + n0) = *reinterpret_cast<uint4*>(o);
}

// ---------------------------------------------------------------------------
// fp16 HMMA GEMM (byte-identical to Round 13):
// C = relu(A[M,K] @ W[N,K]^T + bias). CTA 128x128, BK=64, 3-stage cp.async,
// 8 warps (2Mx4N, 64x32 each). smem stage: A 16K | W 16K = 32K; 3 stages.
// ---------------------------------------------------------------------------
#define STAGE_BYTES 32768
#define HG_SMEM (3 * STAGE_BYTES)

__global__ __launch_bounds__(256, 1)
void hgemm_f16(const __half* __restrict__ A,
               const __half* __restrict__ W,
               const float* __restrict__ bias,
               __half* __restrict__ C,
               int N, int K)
{
    extern __shared__ char smem[];
    const uint32_t sbase = smem_u32(smem);
    const int tid  = threadIdx.x;
    const int wid  = tid >> 5;
    const int lane = tid & 31;
    const int warpM = wid & 1;
    const int warpN = wid >> 1;
    const int m0 = blockIdx.y * 128;
    const int n0 = blockIdx.x * 128;

    // cp.async: 4 16B chunks per thread per plane per stage
    const char* gA[4]; const char* gW[4];
    uint32_t soff[4];
#pragma unroll
    for (int j = 0; j < 4; ++j) {
        int ci = tid + (j << 8);             // 0..1023
        int row = ci >> 3, ch = ci & 7;
        gA[j] = (const char*)(A + (size_t)(m0 + row) * K + (ch << 3));
        gW[j] = (const char*)(W + (size_t)(n0 + row) * K + (ch << 3));
        soff[j] = (uint32_t)(row * 128 + ((ch ^ (row & 7)) << 4));
    }

    // ldmatrix lane addressing
    const int laneA = lane & 15;
    const uint32_t aRow  = (uint32_t)(warpM * 64 + laneA) * 128;
    const uint32_t aRm   = (uint32_t)(laneA & 7);
    const uint32_t aHalf = (uint32_t)(lane >> 4);
    const uint32_t bR    = (uint32_t)(lane & 7);
    const uint32_t bHalf = (uint32_t)((lane >> 3) & 1);
    const uint32_t bSub  = (uint32_t)((lane >> 4) & 1);
    const uint32_t bRowB = (uint32_t)(warpN * 32 + bSub * 8 + bR) * 128;

    float acc[4][4][4];
#pragma unroll
    for (int mt = 0; mt < 4; ++mt)
#pragma unroll
        for (int nt = 0; nt < 4; ++nt)
#pragma unroll
            for (int r = 0; r < 4; ++r) acc[mt][nt][r] = 0.f;

    const int nK = K >> 6;

    // preload stages 0,1
#pragma unroll
    for (int s = 0; s < 2; ++s) {
        uint32_t st = sbase + s * STAGE_BYTES;
        const uint32_t gadd = (uint32_t)s * 128;
#pragma unroll
        for (int j = 0; j < 4; ++j) {
            CP_ASYNC16(st + soff[j],         gA[j] + gadd);
            CP_ASYNC16(st + 16384 + soff[j], gW[j] + gadd);
        }
        CP_COMMIT();
    }

    int sidx = 0;                    // kb % 3
    int pidx = 2;                    // (kb+2) % 3
    for (int kb = 0; kb < nK; ++kb) {
        const int pf = kb + 2;
        if (pf < nK) {
            uint32_t st = sbase + pidx * STAGE_BYTES;
            const uint32_t gadd = (uint32_t)pf * 128;
#pragma unroll
            for (int j = 0; j < 4; ++j) {
                CP_ASYNC16(st + soff[j],         gA[j] + gadd);
                CP_ASYNC16(st + 16384 + soff[j], gW[j] + gadd);
            }
        }
        CP_COMMIT();                 // possibly-empty group keeps ordering
        CP_WAIT2();
        __syncthreads();

        const uint32_t st = sbase + sidx * STAGE_BYTES;
#pragma unroll
        for (int ks = 0; ks < 4; ++ks) {
            uint32_t a[4][4], b[2][4];
            const uint32_t aCh = (uint32_t)(ks * 2) + aHalf;
            const uint32_t bCh = (uint32_t)(ks * 2) + bHalf;
#pragma unroll
            for (int mt = 0; mt < 4; ++mt)
                LDSM4(a[mt], st + aRow + (uint32_t)(mt * 2048) + ((aCh ^ aRm) << 4));
#pragma unroll
            for (int p = 0; p < 2; ++p)
                LDSM4(b[p], st + 16384 + bRowB + (uint32_t)(p * 2048) + ((bCh ^ bR) << 4));
#pragma unroll
            for (int mt = 0; mt < 4; ++mt) {
                MMA16816(acc[mt][0], a[mt], b[0][0], b[0][1]);
                MMA16816(acc[mt][1], a[mt], b[0][2], b[0][3]);
                MMA16816(acc[mt][2], a[mt], b[1][0], b[1][1]);
                MMA16816(acc[mt][3], a[mt], b[1][2], b[1][3]);
            }
        }
        sidx = (sidx == 2) ? 0 : sidx + 1;
        pidx = (pidx == 2) ? 0 : pidx + 1;
    }

    // epilogue: bias + relu -> fp16 plane
    const int g = lane >> 2, t = lane & 3;
#pragma unroll
    for (int mt = 0; mt < 4; ++mt) {
        const int r0 = m0 + warpM * 64 + mt * 16 + g;
        const int r1 = r0 + 8;
#pragma unroll
        for (int nt = 0; nt < 4; ++nt) {
            const int col = n0 + warpN * 32 + nt * 8 + 2 * t;
            float2 bs = *reinterpret_cast<const float2*>(&bias[col]);
            __half2 p0 = __floats2half2_rn(fmaxf(acc[mt][nt][0] + bs.x, 0.f),
                                           fmaxf(acc[mt][nt][1] + bs.y, 0.f));
            __half2 p1 = __floats2half2_rn(fmaxf(acc[mt][nt][2] + bs.x, 0.f),
                                           fmaxf(acc[mt][nt][3] + bs.y, 0.f));
            *reinterpret_cast<uint32_t*>(C + (size_t)r0 * N + col) =
                *reinterpret_cast<uint32_t*>(&p0);
            *reinterpret_cast<uint32_t*>(C + (size_t)r1 * N + col) =
                *reinterpret_cast<uint32_t*>(&p1);
        }
    }
}

// ---------------------------------------------------------------------------
// Heads: warp-per-row dot products, fp32 weights staged in smem.
// Block: 1024 threads = 32 warps = 32 batch rows. grid = 512.
// smem: W51 fp32 [20*1024] | W52 fp32 [11*1024] | bias[31]  (~124 KB)
// Numerics identical to Round-13 heads (fp16 A -> fp32, fp32 W, fp32 acc).
// ---------------------------------------------------------------------------
#define HEADS_SMEM (31 * 1024 * 4 + 64 * 4)

__global__ __launch_bounds__(1024, 1)
void heads_warp(const __half* __restrict__ h41,
                const __half* __restrict__ h42,
                const float* __restrict__ W51, const float* __restrict__ b51,
                const float* __restrict__ W52, const float* __restrict__ b52,
                float* __restrict__ x51, float* __restrict__ x52)
{
    extern __shared__ float hs[];
    float* w51s = hs;                 // 20*1024
    float* w52s = hs + 20 * 1024;     // 11*1024
    float* bs   = hs + 31 * 1024;     // 31

    const int tid = threadIdx.x;
    for (int i = tid; i < 20 * 1024 / 4; i += 1024)
        reinterpret_cast<float4*>(w51s)[i] = reinterpret_cast<const float4*>(W51)[i];
    for (int i = tid; i < 11 * 1024 / 4; i += 1024)
        reinterpret_cast<float4*>(w52s)[i] = reinterpret_cast<const float4*>(W52)[i];
    if (tid < 20) bs[tid] = b51[tid];
    else if (tid < 31) bs[tid] = b52[tid - 20];
    __syncthreads();

    const int wid = tid >> 5, lane = tid & 31;
    const int row = blockIdx.x * 32 + wid;

    // load A rows: each lane holds halfs [lane*32, lane*32+32) as fp32
    float a1[32], a2[32];
    {
        const __half2* p1 = reinterpret_cast<const __half2*>(h41 + (size_t)row * 1024) + lane * 16;
        const __half2* p2 = reinterpret_cast<const __half2*>(h42 + (size_t)row * 1024) + lane * 16;
#pragma unroll
        for (int i = 0; i < 16; ++i) {
            float2 v1 = __half22float2(p1[i]);
            float2 v2 = __half22float2(p2[i]);
            a1[2 * i] = v1.x; a1[2 * i + 1] = v1.y;
            a2[2 * i] = v2.x; a2[2 * i + 1] = v2.y;
        }
    }

    // x51: 20 outputs from a1 . W51[n]
    for (int n = 0; n < 20; ++n) {
        const float4* wr = reinterpret_cast<const float4*>(w51s + n * 1024 + lane * 32);
        float acc = 0.f;
#pragma unroll
        for (int i = 0; i < 8; ++i) {
            float4 w = wr[i];
            acc = fmaf(a1[4 * i + 0], w.x, acc);
            acc = fmaf(a1[4 * i + 1], w.y, acc);
            acc = fmaf(a1[4 * i + 2], w.z, acc);
            acc = fmaf(a1[4 * i + 3], w.w, acc);
        }
#pragma unroll
        for (int o = 16; o > 0; o >>= 1) acc += __shfl_xor_sync(0xFFFFFFFFu, acc, o);
        if (lane == 0) x51[(size_t)row * 20 + n] = acc + bs[n];
    }

    // x52: 11 outputs from a2 . W52[n], 4*sigmoid applied
    for (int n = 0; n < 11; ++n) {
        const float4* wr = reinterpret_cast<const float4*>(w52s + n * 1024 + lane * 32);
        float acc = 0.f;
#pragma unroll
        for (int i = 0; i < 8; ++i) {
            float4 w = wr[i];
            acc = fmaf(a2[4 * i + 0], w.x, acc);
            acc = fmaf(a2[4 * i + 1], w.y, acc);
            acc = fmaf(a2[4 * i + 2], w.z, acc);
            acc = fmaf(a2[4 * i + 3], w.w, acc);
        }
#pragma unroll
        for (int o = 16; o > 0; o >>= 1) acc += __shfl_xor_sync(0xFFFFFFFFu, acc, o);
        if (lane == 0) {
            float v = acc + bs[20 + n];
            x52[(size_t)row * 11 + n] = 4.f / (1.f + expf(-v));
        }
    }
}

// ---------------- fused CBF-QP epilogue (Round-13 interface) ----------------
__global__ void final_kernel(const float* __restrict__ x,
                             const float* __restrict__ mean,
                             const float* __restrict__ stdv,
                             const float* __restrict__ mean_label,
                             const float* __restrict__ std_label,
                             const float* __restrict__ x51,
                             const float* __restrict__ x52,
                             const float* __restrict__ wt,
                             float* __restrict__ out)
{
    int b = blockIdx.x * blockDim.x + threadIdx.x;
    if (b >= BATCH) return;

    float4 xv = reinterpret_cast<const float4*>(x)[b];
    float th1 = xv.x * stdv[0] + mean[0];
    float w1v = xv.y * stdv[1] + mean[1];
    float th2 = xv.z * stdv[2] + mean[2];
    float w2v = xv.w * stdv[3] + mean[3];

    float s1, c1, s2, c2;
    sincosf(th1, &s1, &c1);
    sincosf(th2, &s2, &c2);

    const float Lc = 3.0f;
    float px = Lc * c1 + Lc * c2;
    float py = Lc * s1 + Lc * s2 - 7.0f;
    float vx = -Lc * s1 * w1v - Lc * s2 * w2v;
    float vy =  Lc * c1 * w1v + Lc * c2 * w2v;
    float barrier = px * px + py * py - 16.0f;
    float b_dot = 2.0f * (px * vx + py * vy);
    float Lf2b = 2.0f * vx * vx + 2.0f * vy * vy
               + 2.0f * px * (-Lc * c1 * w1v * w1v - Lc * c2 * w2v * w2v)
               + 2.0f * py * (-Lc * s1 * w1v * w1v - Lc * s2 * w2v * w2v);
    float g1 = 2.0f * px * (-Lc * s1) + 2.0f * py * (Lc * c1);
    float g2 = 2.0f * px * (-Lc * s2) + 2.0f * py * (Lc * c2);
    float Gx = -g1, Gy = -g2;
    float Gdot = g1 * g1 + g2 * g2;

    float wmax = wt[0];
#pragma unroll
    for (int h = 1; h < 10; h++) wmax = fmaxf(wmax, wt[h]);
    float wv[10], wsum = 0.f;
#pragma unroll
    for (int h = 0; h < 10; h++) { wv[h] = expf(wt[h] - wmax); wsum += wv[h]; }
    float winv = 1.f / wsum;

    float alpha = x52[(size_t)b * 11 + 0];
    float ax = 0.f, ay = 0.f;
#pragma unroll
    for (int h = 0; h < 10; h++) {
        float beta = x52[(size_t)b * 11 + 1 + h];
        float ux = -x51[(size_t)b * 20 + 2 * h];
        float uy = -x51[(size_t)b * 20 + 2 * h + 1];
        float hv = Lf2b + (alpha + beta) * b_dot + alpha * beta * barrier;
        float viol = ux * Gx + uy * Gy - hv;
        float lam = fmaxf(viol / Gdot, 0.f);
        float wh = wv[h] * winv;
        ax = fmaf(wh, ux - lam * Gx, ax);
        ay = fmaf(wh, uy - lam * Gy, ay);
    }
    out[(size_t)b * 2 + 0] = (ax - mean_label[0]) / std_label[0];
    out[(size_t)b * 2 + 1] = (ay - mean_label[1]) / std_label[1];
}

// ---------------- kernel_launch ----------------
extern "C" void kernel_launch(void* const* d_in, const int* in_sizes, int n_in,
                              void* d_out, int out_size)
{
    (void)in_sizes; (void)n_in; (void)out_size;

    const float* x          = (const float*)d_in[0];
    const float* mean       = (const float*)d_in[2];
    const float* stdv       = (const float*)d_in[3];
    const float* mean_label = (const float*)d_in[4];
    const float* std_label  = (const float*)d_in[5];
    const float* W1  = (const float*)d_in[6];   const float* b1  = (const float*)d_in[7];
    const float* W2  = (const float*)d_in[8];   const float* b2  = (const float*)d_in[9];
    const float* W31 = (const float*)d_in[10];  const float* b31 = (const float*)d_in[11];
    const float* W32 = (const float*)d_in[12];  const float* b32 = (const float*)d_in[13];
    const float* W41 = (const float*)d_in[14];  const float* b41 = (const float*)d_in[15];
    const float* W42 = (const float*)d_in[16];  const float* b42 = (const float*)d_in[17];
    const float* W51 = (const float*)d_in[18];  const float* b51 = (const float*)d_in[19];
    const float* W52 = (const float*)d_in[20];  const float* b52 = (const float*)d_in[21];
    const float* wt  = (const float*)d_in[22];
    float* out = (float*)d_out;

    static float *bufA = nullptr, *bufB = nullptr, *bufC = nullptr,
                 *x51p = nullptr, *x52p = nullptr;
    static __half* whp = nullptr;
    if (!bufA) {
        cudaGetSymbolAddress((void**)&bufA, g_bufA);
        cudaGetSymbolAddress((void**)&bufB, g_bufB);
        cudaGetSymbolAddress((void**)&bufC, g_bufC);
        cudaGetSymbolAddress((void**)&x51p, g_x51);
        cudaGetSymbolAddress((void**)&x52p, g_x52);
        cudaGetSymbolAddress((void**)&whp, g_wh);
        cudaFuncSetAttribute(hgemm_f16, cudaFuncAttributeMaxDynamicSharedMemorySize, HG_SMEM);
        cudaFuncSetAttribute(heads_warp, cudaFuncAttributeMaxDynamicSharedMemorySize, HEADS_SMEM);
    }

    // fp16 activation planes inside the fp32 arenas (Round-13 layout)
    __half* h1  = (__half*)bufA;
    __half* h2  = (__half*)bufB;
    __half* h31 = (__half*)bufC;
    __half* h32 = (__half*)bufC + (size_t)16777216;
    __half* h41 = (__half*)bufA;                      // bufA free after GEMM2
    __half* h42 = (__half*)bufA + (size_t)16777216;

    __half* W2h  = whp;
    __half* W31h = whp + 4194304;
    __half* W32h = whp + 6291456;
    __half* W41h = whp + 8388608;
    __half* W42h = whp + 9437184;

    dim3 t256(256);

    // all weight conversions in one launch
    wconvert_kernel<<<10240, t256>>>(W2, W31, W32, W41, W42, whp);

    // layer 1
    layer1_kernel<<<BATCH, t256>>>(x, W1, b1, h1);

    // big GEMMs (single-product fp16 HMMA, Round-13 kernel)
    hgemm_f16<<<dim3(16, 128), t256, HG_SMEM>>>(h1,  W2h,  b2,  h2,  2048, 2048);
    hgemm_f16<<<dim3(8, 128),  t256, HG_SMEM>>>(h2,  W31h, b31, h31, 1024, 2048);
    hgemm_f16<<<dim3(8, 128),  t256, HG_SMEM>>>(h2,  W32h, b32, h32, 1024, 2048);
    hgemm_f16<<<dim3(8, 128),  t256, HG_SMEM>>>(h31, W41h, b41, h41, 1024, 1024);
    hgemm_f16<<<dim3(8, 128),  t256, HG_SMEM>>>(h32, W42h, b42, h42, 1024, 1024);

    // heads: warp-per-row dot products (fp32 weights in smem)
    heads_warp<<<512, 1024, HEADS_SMEM>>>(h41, h42, W51, b51, W52, b52, x51p, x52p);

    // fused CBF-QP epilogue
    final_kernel<<<BATCH / 256, 256>>>(x, mean, stdv, mean_label, std_label,
                                       x51p, x52p, wt, out);
}